// round 14
// baseline (speedup 1.0000x reference)
#include <cuda_runtime.h>
#include <cuda_fp16.h>
#include <math.h>
#include <stdint.h>

// loss = mean_n [ logsumexp_m( q_n . t_m ) - q_n . t_n ],  q = logits - log(noise)
// N = M = 16384, D = 64.
// Single-term fp16 mma.sync; 4x4 warp grid; fixed-shift Schraudolph softmax;
// HALF-TILE SOFTWARE PIPELINE: MMA pass(mt=0), MMA pass(mt=1), then epilogue
// of mt=0 overlaps pass-1's tensor drain. 4-deep cp.async.bulk tile ring.

#define NTOT    16384
#define DIM     64
#define TM      128
#define TN      128
#define NTILES  (NTOT / TN)         // 128
#define NBLOCKS (NTOT / TM)         // 128
#define NTHREADS 512
#define CSHIFT 50.0f

// Schraudolph: e^(v-C) ~ bits(round(v*A + B)), B includes -C*A and the
// zero-mean-error offset (-0.0563*2^23). Negatives saturate to 0 in cvt.u32.
#define SCH_A 12102203.0f
#define SCH_B 459770612.0f

__device__ __align__(128) unsigned char g_thf[(size_t)NTOT * 128];
__device__ float g_partial[NBLOCKS];
__device__ unsigned int g_done;

// ---------------- PTX helpers ----------------
static __device__ __forceinline__ uint32_t smem_u32(const void* p) {
    uint32_t a;
    asm("{ .reg .u64 t; cvta.to.shared.u64 t, %1; cvt.u32.u64 %0, t; }"
        : "=r"(a) : "l"(p));
    return a;
}
static __device__ __forceinline__ float schexp(float v) {
    uint32_t i;
    float r = fmaf(v, SCH_A, SCH_B);
    asm("cvt.rni.u32.f32 %0, %1;" : "=r"(i) : "f"(r));
    return __uint_as_float(i);
}
#define MBAR_INIT(a, c) \
    asm volatile("mbarrier.init.shared.b64 [%0], %1;" :: "r"(a), "r"(c) : "memory")
#define MBAR_EXPECT(a, b) \
    asm volatile("mbarrier.arrive.expect_tx.shared.b64 _, [%0], %1;" :: "r"(a), "r"(b) : "memory")
#define MBAR_ARRIVE(a) \
    asm volatile("mbarrier.arrive.shared.b64 _, [%0];" :: "r"(a) : "memory")
#define MBAR_WAIT(a, ph) do {                                                        \
    uint32_t _m = (a), _p = (ph), _d;                                                \
    asm volatile("{ .reg .pred p; mbarrier.try_wait.parity.acquire.cta.shared::cta.b64 p, [%1], %2; selp.b32 %0,1,0,p; }" \
                 : "=r"(_d) : "r"(_m), "r"(_p) : "memory");                          \
    if (!_d) {                                                                       \
        asm volatile("{ .reg .pred P1; WL%=: mbarrier.try_wait.parity.acquire.cta.shared::cta.b64 P1, [%0], %1, 0x989680; @P1 bra.uni WD%=; bra.uni WL%=; WD%=: }" \
                     :: "r"(_m), "r"(_p) : "memory");                                \
    }                                                                                \
} while (0)

static __device__ __forceinline__ void bulk_g2s(uint32_t dst, const void* src,
                                                uint32_t bytes, uint32_t mbar) {
    uint64_t g;
    asm("cvta.to.global.u64 %0, %1;" : "=l"(g) : "l"(src));
    asm volatile("cp.async.bulk.shared::cta.global.mbarrier::complete_tx::bytes [%0], [%1], %2, [%3];"
                 :: "r"(dst), "l"(g), "r"(bytes), "r"(mbar) : "memory");
}

#define LDSM4(r, a) \
    asm volatile("ldmatrix.sync.aligned.m8n8.x4.shared.b16 {%0,%1,%2,%3}, [%4];" \
                 : "=r"((r)[0]), "=r"((r)[1]), "=r"((r)[2]), "=r"((r)[3]) : "r"(a))

#define MMA16816(d, a, b0, b1) \
    asm volatile("mma.sync.aligned.m16n8k16.row.col.f32.f16.f16.f32 " \
                 "{%0,%1,%2,%3}, {%4,%5,%6,%7}, {%8,%9}, {%0,%1,%2,%3};" \
                 : "+f"((d)[0]), "+f"((d)[1]), "+f"((d)[2]), "+f"((d)[3]) \
                 : "r"((a)[0]), "r"((a)[1]), "r"((a)[2]), "r"((a)[3]), \
                   "r"(b0), "r"(b1))

#define MMA16816Z(d, a, b0, b1) \
    asm volatile("mma.sync.aligned.m16n8k16.row.col.f32.f16.f16.f32 " \
                 "{%0,%1,%2,%3}, {%4,%5,%6,%7}, {%8,%9}, {%10,%10,%10,%10};" \
                 : "=f"((d)[0]), "=f"((d)[1]), "=f"((d)[2]), "=f"((d)[3]) \
                 : "r"((a)[0]), "r"((a)[1]), "r"((a)[2]), "r"((a)[3]), \
                   "r"(b0), "r"(b1), "f"(0.0f))

static __device__ __forceinline__ uint32_t pack_h2(float a, float b) {
    __half2 h = __floats2half2_rn(a, b);
    return *reinterpret_cast<uint32_t*>(&h);
}

// ---------------- prep ----------------
__global__ void __launch_bounds__(256) prep_targets(const float* __restrict__ tg) {
    int idx = blockIdx.x * 256 + threadIdx.x;
    int row = idx >> 3, c = idx & 7;
    const float4* p = reinterpret_cast<const float4*>(tg + (size_t)row * DIM + c * 8);
    float4 a = p[0], b = p[1];
    uint4 u = make_uint4(pack_h2(a.x, a.y), pack_h2(a.z, a.w),
                         pack_h2(b.x, b.y), pack_h2(b.z, b.w));
    int slot = row * 8 + (c ^ (row & 7));
    reinterpret_cast<uint4*>(g_thf)[slot] = u;
}

// SMEM: [0,16K) q fp16, [16K + s*16K) tile ring s=0..3, [80K) mbarriers
#define QOFF  0u
#define TBUF(s) (16384u + (uint32_t)(s) * 16384u)
#define BARO  81920u
#define SMEM_BYTES (81920 + 128)

// one MMA pass for one mt half (reloads B per k)
static __device__ __forceinline__ void mma_pass(
    float (&acc)[4][4], uint32_t th_base, const uint32_t (&Amt)[4][4],
    const uint32_t (&swk)[4])
{
#pragma unroll
    for (int k = 0; k < 4; k++) {
        uint32_t B[2][4];
        LDSM4(B[0], th_base + swk[k]);
        LDSM4(B[1], th_base + 2048u + swk[k]);
        if (k == 0) {
#pragma unroll
            for (int nt = 0; nt < 4; nt++) {
                const int g = nt >> 1, su = nt & 1;
                MMA16816Z(acc[nt], Amt[0], B[g][su], B[g][2 + su]);
            }
        } else {
#pragma unroll
            for (int nt = 0; nt < 4; nt++) {
                const int g = nt >> 1, su = nt & 1;
                MMA16816(acc[nt], Amt[k], B[g][su], B[g][2 + su]);
            }
        }
    }
}

// fixed-shift epilogue for one mt half (+diag capture on the diagonal tile)
static __device__ __forceinline__ void epilogue_half(
    const float (&acc)[4][4], int mt, int t, int b, int wr, int wc, int lane,
    float (&ss)[4], float (&diagv)[4])
{
    if (t == b) {
#pragma unroll
        for (int e = 0; e < 2; e++) {
            const int rloc = wr * 32 + mt * 16 + e * 8 + (lane >> 2);
            const int cw = rloc - wc * 32;
            if (cw >= 0 && cw < 32) {
                const int nt = cw >> 3;
                if (((cw >> 1) & 3) == (lane & 3))
                    diagv[mt * 2 + e] = acc[nt][e * 2 + (cw & 1)];
            }
        }
    }
#pragma unroll
    for (int e = 0; e < 2; e++) {
        const int er = e * 2;
        float s0 = 0.f, s1 = 0.f;
#pragma unroll
        for (int nt = 0; nt < 4; nt++) {
            s0 += schexp(acc[nt][er]);
            s1 += schexp(acc[nt][er + 1]);
        }
        ss[mt * 2 + e] += s0 + s1;
    }
}

__global__ void __launch_bounds__(NTHREADS, 1)
infonce_mma(const float* __restrict__ logits, const float* __restrict__ noise,
            float* __restrict__ out) {
    extern __shared__ unsigned char smem[];
    const uint32_t sb = smem_u32(smem);
    const int tid = threadIdx.x, wid = tid >> 5, lane = tid & 31;
    const int b = blockIdx.x;

    if (tid == 0) {
#pragma unroll
        for (int s = 0; s < 4; s++) {
            MBAR_INIT(sb + BARO + s * 8, 1);
            MBAR_INIT(sb + BARO + 32 + s * 8, 16);
        }
    }

    // ---- q prologue: q = logits - log(noise) -> fp16, swizzled ----
#pragma unroll
    for (int i = 0; i < 2; i++) {
        int ch = tid + NTHREADS * i;
        int row = ch >> 3, c = ch & 7;
        const float4* p = reinterpret_cast<const float4*>(
            logits + (size_t)(b * TM + row) * DIM + c * 8);
        float4 a = p[0], bb = p[1];
        float x[8] = {a.x, a.y, a.z, a.w, bb.x, bb.y, bb.z, bb.w};
#pragma unroll
        for (int j = 0; j < 8; j++) x[j] -= logf(noise[c * 8 + j]);
        uint4 u = make_uint4(pack_h2(x[0], x[1]), pack_h2(x[2], x[3]),
                             pack_h2(x[4], x[5]), pack_h2(x[6], x[7]));
        uint32_t off = (uint32_t)row * 128u + (uint32_t)((c ^ (row & 7)) * 16);
        *reinterpret_cast<uint4*>(smem + QOFF + off) = u;
    }

    if (tid == 0) {
#pragma unroll
        for (int s = 0; s < 4; s++) {
            MBAR_EXPECT(sb + BARO + s * 8, 16384);
            bulk_g2s(sb + TBUF(s), g_thf + (size_t)s * 16384, 16384, sb + BARO + s * 8);
        }
    }
    __syncthreads();

    // warp grid: 4 x 4; warp tile = 32 rows x 32 cols
    const int wr = wid & 3, wc = wid >> 2;
    const int lrow  = lane & 15;
    const int lchk  = lane >> 4;
    const int swrow = lane & 7;

    uint32_t swk[4];
#pragma unroll
    for (int k = 0; k < 4; k++)
        swk[k] = (uint32_t)(((k * 2 + lchk) ^ swrow) << 4);

    uint32_t A[2][4][4];
#pragma unroll
    for (int mt = 0; mt < 2; mt++) {
        const uint32_t a_base = sb + QOFF +
            (uint32_t)(wr * 32 + mt * 16 + lrow) * 128u;
#pragma unroll
        for (int k = 0; k < 4; k++)
            LDSM4(A[mt][k], a_base + swk[k]);
    }

    uint32_t tbs[4];
#pragma unroll
    for (int s = 0; s < 4; s++)
        tbs[s] = sb + TBUF(s) + (uint32_t)(wc * 32 + lrow) * 128u;

    float ss[4], diagv[4];
#pragma unroll
    for (int j = 0; j < 4; j++) { ss[j] = 0.0f; diagv[j] = 0.0f; }

    for (int t = 0; t < NTILES; t++) {
        const int s = t & 3;
        const int ph = (t >> 2) & 1;
        MBAR_WAIT(sb + BARO + s * 8, ph);

        float acc0[4][4], acc1[4][4];
        const uint32_t th_base = tbs[s];

        // pass 0 (rows mt=0), pass 1 (rows mt=1)
        mma_pass(acc0, th_base, A[0], swk);
        mma_pass(acc1, th_base, A[1], swk);

        if (lane == 0) MBAR_ARRIVE(sb + BARO + 32 + s * 8);

        // epilogue of mt=0 overlaps pass-1 tensor drain
        epilogue_half(acc0, 0, t, b, wr, wc, lane, ss, diagv);

        // early refill issue (consume arrivals already posted after pass 1)
        if (t + 4 < NTILES && tid == 0) {
            MBAR_WAIT(sb + BARO + 32 + s * 8, ph);
            MBAR_EXPECT(sb + BARO + s * 8, 16384);
            bulk_g2s(sb + TBUF(s), g_thf + (size_t)(t + 4) * 16384, 16384,
                     sb + BARO + s * 8);
        }

        epilogue_half(acc1, 1, t, b, wr, wc, lane, ss, diagv);
    }

    // ---- quad merges (sum + diag), then block reduce over 4 col-groups ----
    __syncthreads();
    float* S = reinterpret_cast<float*>(smem);

#pragma unroll
    for (int j = 0; j < 4; j++) {
        float v = ss[j];
        v += __shfl_xor_sync(0xffffffffu, v, 1);
        v += __shfl_xor_sync(0xffffffffu, v, 2);
        ss[j] = v;
        float d = diagv[j];
        d += __shfl_xor_sync(0xffffffffu, d, 1);
        d += __shfl_xor_sync(0xffffffffu, d, 2);
        diagv[j] = d;
    }
    if ((lane & 3) == 0) {
#pragma unroll
        for (int j = 0; j < 4; j++) {
            const int mt = j >> 1, e = j & 1;
            const int r = wr * 32 + mt * 16 + e * 8 + (lane >> 2);
            S[wc * 128 + r]       = ss[j];
            S[512 + wc * 128 + r] = diagv[j];
        }
    }
    __syncthreads();

    float loss = 0.0f;
    if (tid < 128) {
        float ssum = 0.0f, d = 0.0f;
#pragma unroll
        for (int g = 0; g < 4; g++) {
            ssum += S[g * 128 + tid];
            d    += S[512 + g * 128 + tid];
        }
        loss = CSHIFT + logf(ssum) - d;
    }
#pragma unroll
    for (int o = 16; o > 0; o >>= 1)
        loss += __shfl_xor_sync(0xffffffffu, loss, o);
    __syncthreads();
    if (lane == 0) S[1024 + wid] = loss;
    __syncthreads();

    // ---- fused finalize ----
    __shared__ unsigned int ticket;
    if (tid == 0) {
        float v = 0.0f;
#pragma unroll
        for (int i = 0; i < 16; i++) v += S[1024 + i];
        g_partial[b] = v;
        __threadfence();
        ticket = atomicAdd(&g_done, 1u);
    }
    __syncthreads();
    if (ticket == NBLOCKS - 1) {
        __threadfence();
        float v = (tid < NBLOCKS) ? g_partial[tid] : 0.0f;
#pragma unroll
        for (int o = 16; o > 0; o >>= 1)
            v += __shfl_xor_sync(0xffffffffu, v, o);
        if (lane == 0) S[1056 + wid] = v;
        __syncthreads();
        if (tid == 0) {
            float r = 0.0f;
#pragma unroll
            for (int i = 0; i < 16; i++) r += S[1056 + i];
            out[0] = r / (float)NTOT;
            g_done = 0;
        }
    }
}

extern "C" void kernel_launch(void* const* d_in, const int* in_sizes, int n_in,
                              void* d_out, int out_size) {
    const float* logits  = (const float*)d_in[0];
    const float* targets = (const float*)d_in[1];
    const float* noise   = (const float*)d_in[2];

    cudaFuncSetAttribute(infonce_mma, cudaFuncAttributeMaxDynamicSharedMemorySize, SMEM_BYTES);

    prep_targets<<<NTOT * 8 / 256, 256>>>(targets);
    infonce_mma<<<NBLOCKS, NTHREADS, SMEM_BYTES>>>(logits, noise, (float*)d_out);
}

// round 15
// speedup vs baseline: 1.2588x; 1.2588x over previous
#include <cuda_runtime.h>
#include <cuda_fp16.h>
#include <math.h>
#include <stdint.h>

// loss = mean_n [ logsumexp_m( q_n . t_m ) - q_n . t_n ],  q = logits - log(noise)
// N = M = 16384, D = 64.
// Single-term fp16 mma.sync; 4x4 warp grid; fixed-shift Schraudolph softmax;
// COLUMN-HALF SOFTWARE PIPELINE: pass0 = cols 0-15 (B group 0), pass1 =
// cols 16-31 (B group 1) -- no duplicate B loads -- epilogue of the lo half
// overlaps the hi half's tensor drain. 4-deep cp.async.bulk tile ring.

#define NTOT    16384
#define DIM     64
#define TM      128
#define TN      128
#define NTILES  (NTOT / TN)         // 128
#define NBLOCKS (NTOT / TM)         // 128
#define NTHREADS 512
#define CSHIFT 50.0f

// Schraudolph: e^(v-C) ~ bits(round(v*A + B)); B includes -C*A and the
// zero-mean-error offset. Negatives saturate to 0 in cvt.rni.u32.
#define SCH_A 12102203.0f
#define SCH_B 459770612.0f

__device__ __align__(128) unsigned char g_thf[(size_t)NTOT * 128];
__device__ float g_partial[NBLOCKS];
__device__ unsigned int g_done;

// ---------------- PTX helpers ----------------
static __device__ __forceinline__ uint32_t smem_u32(const void* p) {
    uint32_t a;
    asm("{ .reg .u64 t; cvta.to.shared.u64 t, %1; cvt.u32.u64 %0, t; }"
        : "=r"(a) : "l"(p));
    return a;
}
static __device__ __forceinline__ float schexp(float v) {
    uint32_t i;
    float r = fmaf(v, SCH_A, SCH_B);
    asm("cvt.rni.u32.f32 %0, %1;" : "=r"(i) : "f"(r));
    return __uint_as_float(i);
}
#define MBAR_INIT(a, c) \
    asm volatile("mbarrier.init.shared.b64 [%0], %1;" :: "r"(a), "r"(c) : "memory")
#define MBAR_EXPECT(a, b) \
    asm volatile("mbarrier.arrive.expect_tx.shared.b64 _, [%0], %1;" :: "r"(a), "r"(b) : "memory")
#define MBAR_ARRIVE(a) \
    asm volatile("mbarrier.arrive.shared.b64 _, [%0];" :: "r"(a) : "memory")
#define MBAR_WAIT(a, ph) do {                                                        \
    uint32_t _m = (a), _p = (ph), _d;                                                \
    asm volatile("{ .reg .pred p; mbarrier.try_wait.parity.acquire.cta.shared::cta.b64 p, [%1], %2; selp.b32 %0,1,0,p; }" \
                 : "=r"(_d) : "r"(_m), "r"(_p) : "memory");                          \
    if (!_d) {                                                                       \
        asm volatile("{ .reg .pred P1; WL%=: mbarrier.try_wait.parity.acquire.cta.shared::cta.b64 P1, [%0], %1, 0x989680; @P1 bra.uni WD%=; bra.uni WL%=; WD%=: }" \
                     :: "r"(_m), "r"(_p) : "memory");                                \
    }                                                                                \
} while (0)

static __device__ __forceinline__ void bulk_g2s(uint32_t dst, const void* src,
                                                uint32_t bytes, uint32_t mbar) {
    uint64_t g;
    asm("cvta.to.global.u64 %0, %1;" : "=l"(g) : "l"(src));
    asm volatile("cp.async.bulk.shared::cta.global.mbarrier::complete_tx::bytes [%0], [%1], %2, [%3];"
                 :: "r"(dst), "l"(g), "r"(bytes), "r"(mbar) : "memory");
}

#define LDSM4(r, a) \
    asm volatile("ldmatrix.sync.aligned.m8n8.x4.shared.b16 {%0,%1,%2,%3}, [%4];" \
                 : "=r"((r)[0]), "=r"((r)[1]), "=r"((r)[2]), "=r"((r)[3]) : "r"(a))

#define MMA16816(d, a, b0, b1) \
    asm volatile("mma.sync.aligned.m16n8k16.row.col.f32.f16.f16.f32 " \
                 "{%0,%1,%2,%3}, {%4,%5,%6,%7}, {%8,%9}, {%0,%1,%2,%3};" \
                 : "+f"((d)[0]), "+f"((d)[1]), "+f"((d)[2]), "+f"((d)[3]) \
                 : "r"((a)[0]), "r"((a)[1]), "r"((a)[2]), "r"((a)[3]), \
                   "r"(b0), "r"(b1))

#define MMA16816Z(d, a, b0, b1) \
    asm volatile("mma.sync.aligned.m16n8k16.row.col.f32.f16.f16.f32 " \
                 "{%0,%1,%2,%3}, {%4,%5,%6,%7}, {%8,%9}, {%10,%10,%10,%10};" \
                 : "=f"((d)[0]), "=f"((d)[1]), "=f"((d)[2]), "=f"((d)[3]) \
                 : "r"((a)[0]), "r"((a)[1]), "r"((a)[2]), "r"((a)[3]), \
                   "r"(b0), "r"(b1), "f"(0.0f))

static __device__ __forceinline__ uint32_t pack_h2(float a, float b) {
    __half2 h = __floats2half2_rn(a, b);
    return *reinterpret_cast<uint32_t*>(&h);
}

// ---------------- prep ----------------
__global__ void __launch_bounds__(256) prep_targets(const float* __restrict__ tg) {
    int idx = blockIdx.x * 256 + threadIdx.x;
    int row = idx >> 3, c = idx & 7;
    const float4* p = reinterpret_cast<const float4*>(tg + (size_t)row * DIM + c * 8);
    float4 a = p[0], b = p[1];
    uint4 u = make_uint4(pack_h2(a.x, a.y), pack_h2(a.z, a.w),
                         pack_h2(b.x, b.y), pack_h2(b.z, b.w));
    int slot = row * 8 + (c ^ (row & 7));
    reinterpret_cast<uint4*>(g_thf)[slot] = u;
}

// SMEM: [0,16K) q fp16, [16K + s*16K) tile ring s=0..3, [80K) mbarriers
#define QOFF  0u
#define TBUF(s) (16384u + (uint32_t)(s) * 16384u)
#define BARO  81920u
#define SMEM_BYTES (81920 + 128)

// MMA pass over one COLUMN half h (B fragment group h); acc[mt*2+su]
static __device__ __forceinline__ void mma_pass_col(
    float (&acc)[4][4], uint32_t th_base, int h,
    const uint32_t (&A)[2][4][4], const uint32_t (&swk)[4])
{
    const uint32_t hoff = (uint32_t)(h * 2048);
#pragma unroll
    for (int k = 0; k < 4; k++) {
        uint32_t B[4];
        LDSM4(B, th_base + hoff + swk[k]);
        if (k == 0) {
#pragma unroll
            for (int mt = 0; mt < 2; mt++)
#pragma unroll
                for (int su = 0; su < 2; su++)
                    MMA16816Z(acc[mt * 2 + su], A[mt][0], B[su], B[2 + su]);
        } else {
#pragma unroll
            for (int mt = 0; mt < 2; mt++)
#pragma unroll
                for (int su = 0; su < 2; su++)
                    MMA16816(acc[mt * 2 + su], A[mt][k], B[su], B[2 + su]);
        }
    }
}

// fixed-shift epilogue for one column half (+diag capture)
static __device__ __forceinline__ void epilogue_col(
    const float (&acc)[4][4], int h, int t, int b, int wr, int wc, int lane,
    float (&ss)[4], float (&diagv)[4])
{
    if (t == b) {
#pragma unroll
        for (int j = 0; j < 4; j++) {
            const int mt = j >> 1, e = j & 1;
            const int rloc = wr * 32 + mt * 16 + e * 8 + (lane >> 2);
            const int cw = rloc - wc * 32 - h * 16;   // col within this half
            if (cw >= 0 && cw < 16) {
                const int su = cw >> 3;
                if (((cw >> 1) & 3) == (lane & 3))
                    diagv[j] = acc[mt * 2 + su][e * 2 + (cw & 1)];
            }
        }
    }
#pragma unroll
    for (int j = 0; j < 4; j++) {
        const int mt = j >> 1, er = (j & 1) * 2;
        float s0 = 0.f, s1 = 0.f;
#pragma unroll
        for (int su = 0; su < 2; su++) {
            s0 += schexp(acc[mt * 2 + su][er]);
            s1 += schexp(acc[mt * 2 + su][er + 1]);
        }
        ss[j] += s0 + s1;
    }
}

__global__ void __launch_bounds__(NTHREADS, 1)
infonce_mma(const float* __restrict__ logits, const float* __restrict__ noise,
            float* __restrict__ out) {
    extern __shared__ unsigned char smem[];
    const uint32_t sb = smem_u32(smem);
    const int tid = threadIdx.x, wid = tid >> 5, lane = tid & 31;
    const int b = blockIdx.x;

    if (tid == 0) {
#pragma unroll
        for (int s = 0; s < 4; s++) {
            MBAR_INIT(sb + BARO + s * 8, 1);
            MBAR_INIT(sb + BARO + 32 + s * 8, 16);
        }
    }

    // ---- q prologue ----
#pragma unroll
    for (int i = 0; i < 2; i++) {
        int ch = tid + NTHREADS * i;
        int row = ch >> 3, c = ch & 7;
        const float4* p = reinterpret_cast<const float4*>(
            logits + (size_t)(b * TM + row) * DIM + c * 8);
        float4 a = p[0], bb = p[1];
        float x[8] = {a.x, a.y, a.z, a.w, bb.x, bb.y, bb.z, bb.w};
#pragma unroll
        for (int j = 0; j < 8; j++) x[j] -= logf(noise[c * 8 + j]);
        uint4 u = make_uint4(pack_h2(x[0], x[1]), pack_h2(x[2], x[3]),
                             pack_h2(x[4], x[5]), pack_h2(x[6], x[7]));
        uint32_t off = (uint32_t)row * 128u + (uint32_t)((c ^ (row & 7)) * 16);
        *reinterpret_cast<uint4*>(smem + QOFF + off) = u;
    }

    if (tid == 0) {
#pragma unroll
        for (int s = 0; s < 4; s++) {
            MBAR_EXPECT(sb + BARO + s * 8, 16384);
            bulk_g2s(sb + TBUF(s), g_thf + (size_t)s * 16384, 16384, sb + BARO + s * 8);
        }
    }
    __syncthreads();

    // warp grid: 4 x 4; warp tile = 32 rows x 32 cols
    const int wr = wid & 3, wc = wid >> 2;
    const int lrow  = lane & 15;
    const int lchk  = lane >> 4;
    const int swrow = lane & 7;

    uint32_t swk[4];
#pragma unroll
    for (int k = 0; k < 4; k++)
        swk[k] = (uint32_t)(((k * 2 + lchk) ^ swrow) << 4);

    uint32_t A[2][4][4];
#pragma unroll
    for (int mt = 0; mt < 2; mt++) {
        const uint32_t a_base = sb + QOFF +
            (uint32_t)(wr * 32 + mt * 16 + lrow) * 128u;
#pragma unroll
        for (int k = 0; k < 4; k++)
            LDSM4(A[mt][k], a_base + swk[k]);
    }

    uint32_t tbs[4];
#pragma unroll
    for (int s = 0; s < 4; s++)
        tbs[s] = sb + TBUF(s) + (uint32_t)(wc * 32 + lrow) * 128u;

    float ss[4], diagv[4];
#pragma unroll
    for (int j = 0; j < 4; j++) { ss[j] = 0.0f; diagv[j] = 0.0f; }

    for (int t = 0; t < NTILES; t++) {
        const int s = t & 3;
        const int ph = (t >> 2) & 1;
        MBAR_WAIT(sb + BARO + s * 8, ph);

        float accLo[4][4], accHi[4][4];
        const uint32_t th_base = tbs[s];

        mma_pass_col(accLo, th_base, 0, A, swk);   // cols 0-15
        mma_pass_col(accHi, th_base, 1, A, swk);   // cols 16-31

        if (lane == 0) MBAR_ARRIVE(sb + BARO + 32 + s * 8);

        // lo epilogue overlaps hi pass tensor drain
        epilogue_col(accLo, 0, t, b, wr, wc, lane, ss, diagv);

        if (t + 4 < NTILES && tid == 0) {
            MBAR_WAIT(sb + BARO + 32 + s * 8, ph);
            MBAR_EXPECT(sb + BARO + s * 8, 16384);
            bulk_g2s(sb + TBUF(s), g_thf + (size_t)(t + 4) * 16384, 16384,
                     sb + BARO + s * 8);
        }

        epilogue_col(accHi, 1, t, b, wr, wc, lane, ss, diagv);
    }

    // ---- quad merges (sum + diag), then block reduce over 4 col-groups ----
    __syncthreads();
    float* S = reinterpret_cast<float*>(smem);

#pragma unroll
    for (int j = 0; j < 4; j++) {
        float v = ss[j];
        v += __shfl_xor_sync(0xffffffffu, v, 1);
        v += __shfl_xor_sync(0xffffffffu, v, 2);
        ss[j] = v;
        float d = diagv[j];
        d += __shfl_xor_sync(0xffffffffu, d, 1);
        d += __shfl_xor_sync(0xffffffffu, d, 2);
        diagv[j] = d;
    }
    if ((lane & 3) == 0) {
#pragma unroll
        for (int j = 0; j < 4; j++) {
            const int mt = j >> 1, e = j & 1;
            const int r = wr * 32 + mt * 16 + e * 8 + (lane >> 2);
            S[wc * 128 + r]       = ss[j];
            S[512 + wc * 128 + r] = diagv[j];
        }
    }
    __syncthreads();

    float loss = 0.0f;
    if (tid < 128) {
        float ssum = 0.0f, d = 0.0f;
#pragma unroll
        for (int g = 0; g < 4; g++) {
            ssum += S[g * 128 + tid];
            d    += S[512 + g * 128 + tid];
        }
        loss = CSHIFT + logf(ssum) - d;
    }
#pragma unroll
    for (int o = 16; o > 0; o >>= 1)
        loss += __shfl_xor_sync(0xffffffffu, loss, o);
    __syncthreads();
    if (lane == 0) S[1024 + wid] = loss;
    __syncthreads();

    // ---- fused finalize ----
    __shared__ unsigned int ticket;
    if (tid == 0) {
        float v = 0.0f;
#pragma unroll
        for (int i = 0; i < 16; i++) v += S[1024 + i];
        g_partial[b] = v;
        __threadfence();
        ticket = atomicAdd(&g_done, 1u);
    }
    __syncthreads();
    if (ticket == NBLOCKS - 1) {
        __threadfence();
        float v = (tid < NBLOCKS) ? g_partial[tid] : 0.0f;
#pragma unroll
        for (int o = 16; o > 0; o >>= 1)
            v += __shfl_xor_sync(0xffffffffu, v, o);
        if (lane == 0) S[1056 + wid] = v;
        __syncthreads();
        if (tid == 0) {
            float r = 0.0f;
#pragma unroll
            for (int i = 0; i < 16; i++) r += S[1056 + i];
            out[0] = r / (float)NTOT;
            g_done = 0;
        }
    }
}

extern "C" void kernel_launch(void* const* d_in, const int* in_sizes, int n_in,
                              void* d_out, int out_size) {
    const float* logits  = (const float*)d_in[0];
    const float* targets = (const float*)d_in[1];
    const float* noise   = (const float*)d_in[2];

    cudaFuncSetAttribute(infonce_mma, cudaFuncAttributeMaxDynamicSharedMemorySize, SMEM_BYTES);

    prep_targets<<<NTOT * 8 / 256, 256>>>(targets);
    infonce_mma<<<NBLOCKS, NTHREADS, SMEM_BYTES>>>(logits, noise, (float*)d_out);
}

// round 16
// speedup vs baseline: 1.4238x; 1.1311x over previous
#include <cuda_runtime.h>
#include <cuda_fp16.h>
#include <math.h>
#include <stdint.h>

// loss = mean_n [ logsumexp_m( q_n . t_m ) - q_n . t_n ],  q = logits - log(noise)
// N = M = 16384, D = 64.
// Single-term fp16 mma.sync; 4x4 warp grid; fixed-shift Schraudolph softmax.
// BALANCED PERSISTENT GRID: 148 CTAs statically own contiguous ranges of the
// 16384 (stripe,tile) units (110-111 each, <=2 stripes). Fixed shift makes
// partial row sums mergeable: flushed via atomicAdd into per-row buffers;
// last CTA does the log+reduce. Tile loop identical to the 116.8us kernel.

#define NTOT    16384
#define DIM     64
#define TM      128
#define TN      128
#define NSTRIPES (NTOT / TM)        // 128
#define NTILES  (NTOT / TN)         // 128
#define NUNITS  (NSTRIPES * NTILES) // 16384
#define NCTAS   148
#define NTHREADS 512
#define CSHIFT 50.0f

// Schraudolph: e^(v-C) ~ bits(round(v*A + B)); B includes -C*A and the
// zero-mean-error offset. Negatives saturate to 0 in cvt.rni.u32.
#define SCH_A 12102203.0f
#define SCH_B 459770612.0f

__device__ __align__(128) unsigned char g_thf[(size_t)NTOT * 128];
__device__ float g_rowss[NTOT];     // per-row exp-sum accumulators
__device__ float g_rowdiag[NTOT];   // per-row diagonal scores
__device__ unsigned int g_done;

// ---------------- PTX helpers ----------------
static __device__ __forceinline__ uint32_t smem_u32(const void* p) {
    uint32_t a;
    asm("{ .reg .u64 t; cvta.to.shared.u64 t, %1; cvt.u32.u64 %0, t; }"
        : "=r"(a) : "l"(p));
    return a;
}
static __device__ __forceinline__ float schexp(float v) {
    uint32_t i;
    float r = fmaf(v, SCH_A, SCH_B);
    asm("cvt.rni.u32.f32 %0, %1;" : "=r"(i) : "f"(r));
    return __uint_as_float(i);
}
#define MBAR_INIT(a, c) \
    asm volatile("mbarrier.init.shared.b64 [%0], %1;" :: "r"(a), "r"(c) : "memory")
#define MBAR_EXPECT(a, b) \
    asm volatile("mbarrier.arrive.expect_tx.shared.b64 _, [%0], %1;" :: "r"(a), "r"(b) : "memory")
#define MBAR_ARRIVE(a) \
    asm volatile("mbarrier.arrive.shared.b64 _, [%0];" :: "r"(a) : "memory")
#define MBAR_WAIT(a, ph) do {                                                        \
    uint32_t _m = (a), _p = (ph), _d;                                                \
    asm volatile("{ .reg .pred p; mbarrier.try_wait.parity.acquire.cta.shared::cta.b64 p, [%1], %2; selp.b32 %0,1,0,p; }" \
                 : "=r"(_d) : "r"(_m), "r"(_p) : "memory");                          \
    if (!_d) {                                                                       \
        asm volatile("{ .reg .pred P1; WL%=: mbarrier.try_wait.parity.acquire.cta.shared::cta.b64 P1, [%0], %1, 0x989680; @P1 bra.uni WD%=; bra.uni WL%=; WD%=: }" \
                     :: "r"(_m), "r"(_p) : "memory");                                \
    }                                                                                \
} while (0)

static __device__ __forceinline__ void bulk_g2s(uint32_t dst, const void* src,
                                                uint32_t bytes, uint32_t mbar) {
    uint64_t g;
    asm("cvta.to.global.u64 %0, %1;" : "=l"(g) : "l"(src));
    asm volatile("cp.async.bulk.shared::cta.global.mbarrier::complete_tx::bytes [%0], [%1], %2, [%3];"
                 :: "r"(dst), "l"(g), "r"(bytes), "r"(mbar) : "memory");
}

#define LDSM4(r, a) \
    asm volatile("ldmatrix.sync.aligned.m8n8.x4.shared.b16 {%0,%1,%2,%3}, [%4];" \
                 : "=r"((r)[0]), "=r"((r)[1]), "=r"((r)[2]), "=r"((r)[3]) : "r"(a))

#define MMA16816(d, a, b0, b1) \
    asm volatile("mma.sync.aligned.m16n8k16.row.col.f32.f16.f16.f32 " \
                 "{%0,%1,%2,%3}, {%4,%5,%6,%7}, {%8,%9}, {%0,%1,%2,%3};" \
                 : "+f"((d)[0]), "+f"((d)[1]), "+f"((d)[2]), "+f"((d)[3]) \
                 : "r"((a)[0]), "r"((a)[1]), "r"((a)[2]), "r"((a)[3]), \
                   "r"(b0), "r"(b1))

#define MMA16816Z(d, a, b0, b1) \
    asm volatile("mma.sync.aligned.m16n8k16.row.col.f32.f16.f16.f32 " \
                 "{%0,%1,%2,%3}, {%4,%5,%6,%7}, {%8,%9}, {%10,%10,%10,%10};" \
                 : "=f"((d)[0]), "=f"((d)[1]), "=f"((d)[2]), "=f"((d)[3]) \
                 : "r"((a)[0]), "r"((a)[1]), "r"((a)[2]), "r"((a)[3]), \
                   "r"(b0), "r"(b1), "f"(0.0f))

static __device__ __forceinline__ uint32_t pack_h2(float a, float b) {
    __half2 h = __floats2half2_rn(a, b);
    return *reinterpret_cast<uint32_t*>(&h);
}

// ---------------- prep: convert/swizzle targets + zero row accumulators ----
__global__ void __launch_bounds__(256) prep_targets(const float* __restrict__ tg) {
    int idx = blockIdx.x * 256 + threadIdx.x;
    int row = idx >> 3, c = idx & 7;
    const float4* p = reinterpret_cast<const float4*>(tg + (size_t)row * DIM + c * 8);
    float4 a = p[0], b = p[1];
    uint4 u = make_uint4(pack_h2(a.x, a.y), pack_h2(a.z, a.w),
                         pack_h2(b.x, b.y), pack_h2(b.z, b.w));
    int slot = row * 8 + (c ^ (row & 7));
    reinterpret_cast<uint4*>(g_thf)[slot] = u;
    if (idx < NTOT) {
        g_rowss[idx]   = 0.0f;
        g_rowdiag[idx] = 0.0f;
    }
}

// SMEM: [0,16K) q fp16 (doubles as reduce scratch), [16K + s*16K) ring, [80K) mbarriers
#define QOFF  0u
#define TBUF(s) (16384u + (uint32_t)(s) * 16384u)
#define BARO  81920u
#define SMEM_BYTES (81920 + 128)

__global__ void __launch_bounds__(NTHREADS, 1)
infonce_mma(const float* __restrict__ logits, const float* __restrict__ noise,
            float* __restrict__ out) {
    extern __shared__ unsigned char smem[];
    const uint32_t sb = smem_u32(smem);
    const int tid = threadIdx.x, wid = tid >> 5, lane = tid & 31;
    const int c = blockIdx.x;

    const int ubase = (NUNITS * c) / NCTAS;
    const int ulen  = (NUNITS * (c + 1)) / NCTAS - ubase;

    if (tid == 0) {
#pragma unroll
        for (int s = 0; s < 4; s++) {
            MBAR_INIT(sb + BARO + s * 8, 1);        // data ready
            MBAR_INIT(sb + BARO + 32 + s * 8, 16);  // consumed (16 warps)
        }
    }
    __syncthreads();   // barrier init visible

    // prefetch first up-to-4 units
    if (tid == 0) {
#pragma unroll
        for (int s = 0; s < 4; s++) {
            if (s < ulen) {
                MBAR_EXPECT(sb + BARO + s * 8, 16384);
                bulk_g2s(sb + TBUF(s),
                         g_thf + (size_t)((ubase + s) & (NTILES - 1)) * 16384,
                         16384, sb + BARO + s * 8);
            }
        }
    }

    // warp grid: 4 x 4; warp tile = 32 rows x 32 cols
    const int wr = wid & 3, wc = wid >> 2;
    const int lrow  = lane & 15;
    const int lchk  = lane >> 4;
    const int swrow = lane & 7;

    uint32_t swk[4];
#pragma unroll
    for (int k = 0; k < 4; k++)
        swk[k] = (uint32_t)(((k * 2 + lchk) ^ swrow) << 4);

    uint32_t tbs[4];
#pragma unroll
    for (int s = 0; s < 4; s++)
        tbs[s] = sb + TBUF(s) + (uint32_t)(wc * 32 + lrow) * 128u;

    float* S = reinterpret_cast<float*>(smem);   // scratch overlaying q region

    uint32_t A[2][4][4];
    float ss[4], diagv[4];

    int i = 0;
    while (i < ulen) {
        const int stripe = (ubase + i) >> 7;            // current q stripe
        const int segend = min(ulen, ((stripe + 1) << 7) - ubase);

        // ---- stripe prologue: q = logits - log(noise) -> fp16, swizzled ----
        __syncthreads();   // prior uses of q smem / scratch done
#pragma unroll
        for (int it = 0; it < 2; it++) {
            int ch = tid + NTHREADS * it;               // 0..1023
            int row = ch >> 3, cc = ch & 7;
            const float4* p = reinterpret_cast<const float4*>(
                logits + (size_t)(stripe * TM + row) * DIM + cc * 8);
            float4 a = p[0], bb = p[1];
            float x[8] = {a.x, a.y, a.z, a.w, bb.x, bb.y, bb.z, bb.w};
#pragma unroll
            for (int j = 0; j < 8; j++) x[j] -= logf(noise[cc * 8 + j]);
            uint4 u = make_uint4(pack_h2(x[0], x[1]), pack_h2(x[2], x[3]),
                                 pack_h2(x[4], x[5]), pack_h2(x[6], x[7]));
            uint32_t off = (uint32_t)row * 128u + (uint32_t)((cc ^ (row & 7)) * 16);
            *reinterpret_cast<uint4*>(smem + QOFF + off) = u;
        }
        __syncthreads();

        // preload A fragments for this stripe
#pragma unroll
        for (int mt = 0; mt < 2; mt++) {
            const uint32_t a_base = sb + QOFF +
                (uint32_t)(wr * 32 + mt * 16 + lrow) * 128u;
#pragma unroll
            for (int k = 0; k < 4; k++)
                LDSM4(A[mt][k], a_base + swk[k]);
        }
#pragma unroll
        for (int j = 0; j < 4; j++) { ss[j] = 0.0f; diagv[j] = 0.0f; }

        // ---- tile loop over this stripe segment ----
        for (; i < segend; i++) {
            const int t = (ubase + i) & (NTILES - 1);
            const int s = i & 3;
            const int ph = (i >> 2) & 1;
            MBAR_WAIT(sb + BARO + s * 8, ph);

            float acc[8][4];
            const uint32_t th_base = tbs[s];

#pragma unroll
            for (int k = 0; k < 4; k++) {
                uint32_t B[2][4];
                LDSM4(B[0], th_base + swk[k]);
                LDSM4(B[1], th_base + 2048u + swk[k]);
                if (k == 0) {
#pragma unroll
                    for (int mt = 0; mt < 2; mt++)
#pragma unroll
                        for (int nt = 0; nt < 4; nt++) {
                            const int g = nt >> 1, su = nt & 1;
                            MMA16816Z(acc[mt * 4 + nt], A[mt][0], B[g][su], B[g][2 + su]);
                        }
                } else {
#pragma unroll
                    for (int mt = 0; mt < 2; mt++)
#pragma unroll
                        for (int nt = 0; nt < 4; nt++) {
                            const int g = nt >> 1, su = nt & 1;
                            MMA16816(acc[mt * 4 + nt], A[mt][k], B[g][su], B[g][2 + su]);
                        }
                }
            }

            if (lane == 0) MBAR_ARRIVE(sb + BARO + 32 + s * 8);

            // diagonal extraction (tile t == stripe holds this stripe's diagonal)
            if (t == stripe) {
#pragma unroll
                for (int j = 0; j < 4; j++) {
                    const int mt = j >> 1, e = j & 1;
                    const int rloc = wr * 32 + mt * 16 + e * 8 + (lane >> 2);
                    const int cw = rloc - wc * 32;
                    if (cw >= 0 && cw < 32) {
                        const int nt = cw >> 3;
                        if (((cw >> 1) & 3) == (lane & 3))
                            diagv[j] = acc[mt * 4 + nt][e * 2 + (cw & 1)];
                    }
                }
            }

            // fixed-shift Schraudolph softmax accumulation
#pragma unroll
            for (int j = 0; j < 4; j++) {
                const int mt = j >> 1, er = (j & 1) * 2;
                float s0 = 0.f, s1 = 0.f;
#pragma unroll
                for (int nt = 0; nt < 4; nt++) {
                    s0 += schexp(acc[mt * 4 + nt][er]);
                    s1 += schexp(acc[mt * 4 + nt][er + 1]);
                }
                ss[j] += s0 + s1;
            }

            // refill stage s with unit i+4
            if (i + 4 < ulen && tid == 0) {
                MBAR_WAIT(sb + BARO + 32 + s * 8, ph);
                MBAR_EXPECT(sb + BARO + s * 8, 16384);
                bulk_g2s(sb + TBUF(s),
                         g_thf + (size_t)((ubase + i + 4) & (NTILES - 1)) * 16384,
                         16384, sb + BARO + s * 8);
            }
        }

        // ---- stripe flush: merge partials, atomicAdd into row buffers ----
        __syncthreads();   // all epilogues done; q/scratch smem reusable
#pragma unroll
        for (int j = 0; j < 4; j++) {
            float v = ss[j];
            v += __shfl_xor_sync(0xffffffffu, v, 1);
            v += __shfl_xor_sync(0xffffffffu, v, 2);
            ss[j] = v;
            float d = diagv[j];
            d += __shfl_xor_sync(0xffffffffu, d, 1);
            d += __shfl_xor_sync(0xffffffffu, d, 2);
            diagv[j] = d;
        }
        if ((lane & 3) == 0) {
#pragma unroll
            for (int j = 0; j < 4; j++) {
                const int mt = j >> 1, e = j & 1;
                const int r = wr * 32 + mt * 16 + e * 8 + (lane >> 2);
                S[wc * 128 + r]       = ss[j];
                S[512 + wc * 128 + r] = diagv[j];
            }
        }
        __syncthreads();
        if (tid < 128) {
            float ssum = 0.0f, d = 0.0f;
#pragma unroll
            for (int g = 0; g < 4; g++) {
                ssum += S[g * 128 + tid];
                d    += S[512 + g * 128 + tid];
            }
            atomicAdd(&g_rowss[stripe * TM + tid], ssum);
            atomicAdd(&g_rowdiag[stripe * TM + tid], d);
        }
    }

    // ---- fused finalize: last CTA computes per-row loss + reduce ----
    __shared__ unsigned int ticket;
    __syncthreads();
    if (tid == 0) {
        __threadfence();
        ticket = atomicAdd(&g_done, 1u);
    }
    __syncthreads();
    if (ticket == NCTAS - 1) {
        __threadfence();
        float acc = 0.0f;
#pragma unroll
        for (int r = tid; r < NTOT; r += NTHREADS)
            acc += CSHIFT + logf(g_rowss[r]) - g_rowdiag[r];
#pragma unroll
        for (int o = 16; o > 0; o >>= 1)
            acc += __shfl_xor_sync(0xffffffffu, acc, o);
        if (lane == 0) S[1024 + wid] = acc;
        __syncthreads();
        if (tid == 0) {
            float r = 0.0f;
#pragma unroll
            for (int k = 0; k < 16; k++) r += S[1024 + k];
            out[0] = r / (float)NTOT;
            g_done = 0;
        }
    }
}

extern "C" void kernel_launch(void* const* d_in, const int* in_sizes, int n_in,
                              void* d_out, int out_size) {
    const float* logits  = (const float*)d_in[0];
    const float* targets = (const float*)d_in[1];
    const float* noise   = (const float*)d_in[2];

    cudaFuncSetAttribute(infonce_mma, cudaFuncAttributeMaxDynamicSharedMemorySize, SMEM_BYTES);

    prep_targets<<<NTOT * 8 / 256, 256>>>(targets);
    infonce_mma<<<NCTAS, NTHREADS, SMEM_BYTES>>>(logits, noise, (float*)d_out);
}